// round 2
// baseline (speedup 1.0000x reference)
#include <cuda_runtime.h>
#include <cuda_bf16.h>
#include <math.h>

// Problem constants
#define BATCH 2
#define SEQ   2048
#define DIM   1024
#define HEADS 16
#define HD    64
#define MROWS (BATCH*SEQ)      // 4096
#define QKVN  (3*DIM)          // 3072

// Scratch (device globals — no allocation allowed)
__device__ float g_qkv[MROWS * QKVN];   // [B*S, 3D]: q | k | v per row
__device__ float g_ctx[MROWS * DIM];    // [B*S, D] attention output

// ---------------------------------------------------------------------------
// SGEMM with bias: C[M,N] = A[M,K] @ B[K,N] + bias[N]
// 128x128 tile, K-step 8, 256 threads, 8x8 per thread, double-buffered smem.
// Requires M%128==0, N%128==0, K%8==0.
// ---------------------------------------------------------------------------
__global__ __launch_bounds__(256, 2)
void sgemm_bias_kernel(const float* __restrict__ A,
                       const float* __restrict__ B,
                       const float* __restrict__ bias,
                       float* __restrict__ C,
                       int M, int N, int K)
{
    __shared__ float As[2][8][128];   // [k][m]
    __shared__ float Bs[2][8][128];   // [k][n]

    const int tid = threadIdx.x;
    const int tx  = tid & 15;         // 0..15 -> col groups
    const int ty  = tid >> 4;         // 0..15 -> row group
    const int m0  = blockIdx.y * 128;
    const int n0  = blockIdx.x * 128;

    // load-index mapping
    const int arow = tid >> 1;          // 0..127
    const int acol = (tid & 1) * 4;     // 0 or 4
    const int brow = tid >> 5;          // 0..7
    const int bcol = (tid & 31) * 4;    // 0..124

    const float* Aptr = A + (size_t)(m0 + arow) * K + acol;
    const float* Bptr = B + (size_t)brow * N + n0 + bcol;

    // preload tile 0
    {
        float4 av = *(const float4*)Aptr;
        float4 bv = *(const float4*)Bptr;
        As[0][acol+0][arow] = av.x;
        As[0][acol+1][arow] = av.y;
        As[0][acol+2][arow] = av.z;
        As[0][acol+3][arow] = av.w;
        *(float4*)&Bs[0][brow][bcol] = bv;
    }
    __syncthreads();

    float acc[8][8];
    #pragma unroll
    for (int i = 0; i < 8; i++)
        #pragma unroll
        for (int j = 0; j < 8; j++) acc[i][j] = 0.f;

    int buf = 0;
    for (int k0 = 0; k0 < K; k0 += 8) {
        const bool has_next = (k0 + 8) < K;
        float4 an, bn;
        if (has_next) {
            an = *(const float4*)(Aptr + k0 + 8);
            bn = *(const float4*)(Bptr + (size_t)(k0 + 8) * N);
        }
        #pragma unroll
        for (int kk = 0; kk < 8; kk++) {
            float4 a0 = *(float4*)&As[buf][kk][8*ty];
            float4 a1 = *(float4*)&As[buf][kk][8*ty+4];
            float4 b0 = *(float4*)&Bs[buf][kk][4*tx];
            float4 b1 = *(float4*)&Bs[buf][kk][64 + 4*tx];
            float a[8] = {a0.x,a0.y,a0.z,a0.w,a1.x,a1.y,a1.z,a1.w};
            float bb[8] = {b0.x,b0.y,b0.z,b0.w,b1.x,b1.y,b1.z,b1.w};
            #pragma unroll
            for (int i = 0; i < 8; i++)
                #pragma unroll
                for (int j = 0; j < 8; j++)
                    acc[i][j] = fmaf(a[i], bb[j], acc[i][j]);
        }
        if (has_next) {
            const int nb = buf ^ 1;
            As[nb][acol+0][arow] = an.x;
            As[nb][acol+1][arow] = an.y;
            As[nb][acol+2][arow] = an.z;
            As[nb][acol+3][arow] = an.w;
            *(float4*)&Bs[nb][brow][bcol] = bn;
        }
        __syncthreads();
        buf ^= 1;
    }

    // epilogue: + bias, write two float4 groups per row
    float4 bia0 = *(const float4*)(bias + n0 + 4*tx);
    float4 bia1 = *(const float4*)(bias + n0 + 64 + 4*tx);
    #pragma unroll
    for (int i = 0; i < 8; i++) {
        float* Crow = C + (size_t)(m0 + 8*ty + i) * N;
        float4 o0, o1;
        o0.x = acc[i][0] + bia0.x;  o0.y = acc[i][1] + bia0.y;
        o0.z = acc[i][2] + bia0.z;  o0.w = acc[i][3] + bia0.w;
        o1.x = acc[i][4] + bia1.x;  o1.y = acc[i][5] + bia1.y;
        o1.z = acc[i][6] + bia1.z;  o1.w = acc[i][7] + bia1.w;
        *(float4*)(Crow + n0 + 4*tx)      = o0;
        *(float4*)(Crow + n0 + 64 + 4*tx) = o1;
    }
}

// ---------------------------------------------------------------------------
// Flash attention (fp32), per block: 64 queries of one (b,h), full K/V sweep.
// Smem layout (dynamic): Qt[64hd][68] k-major (scaled by 1/8),
// Kt[64hd][68] k-major, Pt[64key][68] key-major, Vs[64key][64] natural.
// 256 threads as 16x16; each computes a 4x4 score/output block.
// ---------------------------------------------------------------------------
#define PADW 68
__global__ __launch_bounds__(256, 2)
void attn_kernel(const float* __restrict__ qkv, float* __restrict__ ctx)
{
    extern __shared__ float sm[];
    float* Qt = sm;                    // 64*68
    float* Kt = sm + 64*PADW;          // 64*68
    float* Pt = sm + 2*64*PADW;        // 64*68
    float* Vs = sm + 3*64*PADW;        // 64*64

    const int tid = threadIdx.x;
    const int tx  = tid & 15;
    const int ty  = tid >> 4;
    const int bh  = blockIdx.y;
    const int b   = bh >> 4;
    const int h   = bh & 15;
    const int s0  = blockIdx.x * 64;

    const float* qb = qkv + (size_t)(b*SEQ + s0) * QKVN + h*HD;

    // Load Q tile transposed (k-major), pre-scaled by 1/sqrt(HD)=0.125
    #pragma unroll
    for (int p = 0; p < 4; p++) {
        int idx = tid + p*256;
        int r   = idx >> 4;          // 0..63 (query row)
        int c4  = (idx & 15) * 4;    // hd offset
        float4 v = *(const float4*)(qb + (size_t)r*QKVN + c4);
        Qt[(c4+0)*PADW + r] = v.x * 0.125f;
        Qt[(c4+1)*PADW + r] = v.y * 0.125f;
        Qt[(c4+2)*PADW + r] = v.z * 0.125f;
        Qt[(c4+3)*PADW + r] = v.w * 0.125f;
    }

    float mrow[4], lrow[4], acc[4][4];
    #pragma unroll
    for (int i = 0; i < 4; i++) {
        mrow[i] = -1e30f; lrow[i] = 0.f;
        #pragma unroll
        for (int j = 0; j < 4; j++) acc[i][j] = 0.f;
    }

    for (int kt = 0; kt < SEQ; kt += 64) {
        const float* kb = qkv + (size_t)(b*SEQ + kt) * QKVN + DIM   + h*HD;
        const float* vb = qkv + (size_t)(b*SEQ + kt) * QKVN + 2*DIM + h*HD;

        __syncthreads();   // previous phase2 done (Kt/Vs/Pt reusable); Qt visible on 1st iter
        #pragma unroll
        for (int p = 0; p < 4; p++) {
            int idx = tid + p*256;
            int r   = idx >> 4;
            int c4  = (idx & 15) * 4;
            float4 kv = *(const float4*)(kb + (size_t)r*QKVN + c4);
            Kt[(c4+0)*PADW + r] = kv.x;
            Kt[(c4+1)*PADW + r] = kv.y;
            Kt[(c4+2)*PADW + r] = kv.z;
            Kt[(c4+3)*PADW + r] = kv.w;
            float4 vv = *(const float4*)(vb + (size_t)r*QKVN + c4);
            *(float4*)&Vs[r*64 + c4] = vv;
        }
        __syncthreads();

        // phase 1: S = (Q/8) @ K^T  (4x4 per thread)
        float s[4][4];
        #pragma unroll
        for (int i = 0; i < 4; i++)
            #pragma unroll
            for (int j = 0; j < 4; j++) s[i][j] = 0.f;
        #pragma unroll 8
        for (int hd = 0; hd < 64; hd++) {
            float4 a4 = *(float4*)&Qt[hd*PADW + 4*ty];
            float4 b4 = *(float4*)&Kt[hd*PADW + 4*tx];
            float a[4] = {a4.x,a4.y,a4.z,a4.w};
            float bb[4] = {b4.x,b4.y,b4.z,b4.w};
            #pragma unroll
            for (int i = 0; i < 4; i++)
                #pragma unroll
                for (int j = 0; j < 4; j++)
                    s[i][j] = fmaf(a[i], bb[j], s[i][j]);
        }

        // online softmax; write P transposed (key-major) to smem
        #pragma unroll
        for (int i = 0; i < 4; i++) {
            float rmax = fmaxf(fmaxf(s[i][0], s[i][1]), fmaxf(s[i][2], s[i][3]));
            #pragma unroll
            for (int off = 8; off >= 1; off >>= 1)
                rmax = fmaxf(rmax, __shfl_xor_sync(0xffffffffu, rmax, off));
            float mnew   = fmaxf(mrow[i], rmax);
            float factor = __expf(mrow[i] - mnew);
            mrow[i] = mnew;
            float ps = 0.f;
            #pragma unroll
            for (int j = 0; j < 4; j++) {
                float pv = __expf(s[i][j] - mnew);
                Pt[(4*tx + j)*PADW + 4*ty + i] = pv;
                ps += pv;
            }
            #pragma unroll
            for (int off = 8; off >= 1; off >>= 1)
                ps += __shfl_xor_sync(0xffffffffu, ps, off);
            lrow[i] = lrow[i] * factor + ps;
            #pragma unroll
            for (int j = 0; j < 4; j++) acc[i][j] *= factor;
        }
        __syncthreads();

        // phase 2: O += P @ V
        #pragma unroll 8
        for (int c = 0; c < 64; c++) {
            float4 a4 = *(float4*)&Pt[c*PADW + 4*ty];
            float4 b4 = *(float4*)&Vs[c*64 + 4*tx];
            float a[4] = {a4.x,a4.y,a4.z,a4.w};
            float bb[4] = {b4.x,b4.y,b4.z,b4.w};
            #pragma unroll
            for (int i = 0; i < 4; i++)
                #pragma unroll
                for (int j = 0; j < 4; j++)
                    acc[i][j] = fmaf(a[i], bb[j], acc[i][j]);
        }
    }

    // finalize and write ctx[B*S, D] at column h*64
    #pragma unroll
    for (int i = 0; i < 4; i++) {
        float inv = 1.f / lrow[i];
        float4 o;
        o.x = acc[i][0]*inv; o.y = acc[i][1]*inv;
        o.z = acc[i][2]*inv; o.w = acc[i][3]*inv;
        size_t row = (size_t)(b*SEQ + s0 + 4*ty + i);
        *(float4*)(ctx + row*DIM + h*HD + 4*tx) = o;
    }
}

// ---------------------------------------------------------------------------
// Launch
// ---------------------------------------------------------------------------
extern "C" void kernel_launch(void* const* d_in, const int* in_sizes, int n_in,
                              void* d_out, int out_size)
{
    const float* x      = (const float*)d_in[0];
    const float* qkv_w  = (const float*)d_in[2];
    const float* qkv_b  = (const float*)d_in[3];
    const float* out_w  = (const float*)d_in[4];
    const float* out_b  = (const float*)d_in[5];
    float* out = (float*)d_out;

    float* qkv; float* ctx;
    cudaGetSymbolAddress((void**)&qkv, g_qkv);
    cudaGetSymbolAddress((void**)&ctx, g_ctx);

    const int attn_smem = (3*64*PADW + 64*64) * (int)sizeof(float);   // 68608 B
    cudaFuncSetAttribute(attn_kernel,
                         cudaFuncAttributeMaxDynamicSharedMemorySize, attn_smem);

    // 1) QKV projection: [4096,3072] = x[4096,1024] @ qkv_w[1024,3072] + b
    sgemm_bias_kernel<<<dim3(QKVN/128, MROWS/128), 256>>>(
        x, qkv_w, qkv_b, qkv, MROWS, QKVN, DIM);

    // 2) attention: grid (S/64 q-tiles, B*H)
    attn_kernel<<<dim3(SEQ/64, BATCH*HEADS), 256, attn_smem>>>(qkv, ctx);

    // 3) output projection: out[4096,1024] = ctx @ out_w + out_b
    sgemm_bias_kernel<<<dim3(DIM/128, MROWS/128), 256>>>(
        ctx, out_w, out_b, out, MROWS, DIM, DIM);
}

// round 5
// speedup vs baseline: 1.3088x; 1.3088x over previous
#include <cuda_runtime.h>
#include <cuda_bf16.h>
#include <cstdint>
#include <math.h>

// Problem constants
#define BATCH 2
#define SEQ   2048
#define DIM   1024
#define HEADS 16
#define HD    64
#define MROWS (BATCH*SEQ)      // 4096
#define QKVN  (3*DIM)          // 3072
#define GK    1024             // K for both GEMMs

// ---------------------------------------------------------------------------
// Scratch (device globals — no allocation allowed)
// ---------------------------------------------------------------------------
__device__ float g_qkv[MROWS * QKVN];       // [B*S, 3D]: q | k | v per row
__device__ float g_ctx[MROWS * DIM];        // [B*S, D] attention output
__device__ __nv_bfloat16 g_ah[MROWS * DIM]; // activation hi split (x, then ctx)
__device__ __nv_bfloat16 g_al[MROWS * DIM]; // activation lo split
__device__ __nv_bfloat16 g_wqh[QKVN * DIM]; // qkv_w^T hi  [N=3072, K=1024]
__device__ __nv_bfloat16 g_wql[QKVN * DIM]; // qkv_w^T lo
__device__ __nv_bfloat16 g_woh[DIM * DIM];  // out_w^T hi  [N=1024, K=1024]
__device__ __nv_bfloat16 g_wol[DIM * DIM];  // out_w^T lo

// ---------------------------------------------------------------------------
// Baseline-PTX helpers (sm_80-era: ldmatrix / mma.sync / cp.async ONLY —
// tcgen05 is rejected by this harness's compute_100 PTX target)
// ---------------------------------------------------------------------------
__device__ __forceinline__ uint32_t smem_to_u32(const void* smem_ptr) {
    uint32_t addr;
    asm("{ .reg .u64 tmp; cvta.to.shared.u64 tmp, %1; cvt.u32.u64 %0, tmp; }"
        : "=r"(addr) : "l"(smem_ptr));
    return addr;
}

#define SWZ(byte_offset) ((byte_offset) ^ (((byte_offset) >> 3) & 0x70))

__device__ __forceinline__ void ldsm_x4(uint32_t& r0, uint32_t& r1,
                                        uint32_t& r2, uint32_t& r3,
                                        uint32_t addr) {
    asm volatile("ldmatrix.sync.aligned.m8n8.x4.shared.b16 {%0,%1,%2,%3}, [%4];"
                 : "=r"(r0), "=r"(r1), "=r"(r2), "=r"(r3) : "r"(addr));
}

__device__ __forceinline__ void mma_bf16(float4& c, const uint32_t a[4],
                                         uint32_t b0, uint32_t b1) {
    asm volatile(
        "mma.sync.aligned.m16n8k16.row.col.f32.bf16.bf16.f32 "
        "{%0,%1,%2,%3}, {%4,%5,%6,%7}, {%8,%9}, {%0,%1,%2,%3};"
        : "+f"(c.x), "+f"(c.y), "+f"(c.z), "+f"(c.w)
        : "r"(a[0]), "r"(a[1]), "r"(a[2]), "r"(a[3]), "r"(b0), "r"(b1));
}

#define CP_ASYNC16(dst, src) \
    asm volatile("cp.async.cg.shared.global [%0], [%1], 16;" \
                 :: "r"(dst), "l"(src))
#define CP_COMMIT() asm volatile("cp.async.commit_group;" ::: "memory")
#define CP_WAIT(n)  asm volatile("cp.async.wait_group %0;" :: "n"(n) : "memory")

// ---------------------------------------------------------------------------
// split kernels: fp32 -> (bf16 hi, bf16 lo)
// ---------------------------------------------------------------------------
struct alignas(8) bf16x4 { __nv_bfloat162 a, b; };

__global__ void split_rows_kernel(const float* __restrict__ in,
                                  __nv_bfloat16* __restrict__ hi,
                                  __nv_bfloat16* __restrict__ lo)
{
    int t = blockIdx.x * blockDim.x + threadIdx.x;
    float4 v = *(const float4*)(in + (size_t)t * 4);
    __nv_bfloat162 h01 = __floats2bfloat162_rn(v.x, v.y);
    __nv_bfloat162 h23 = __floats2bfloat162_rn(v.z, v.w);
    float2 f01 = __bfloat1622float2(h01);
    float2 f23 = __bfloat1622float2(h23);
    __nv_bfloat162 l01 = __floats2bfloat162_rn(v.x - f01.x, v.y - f01.y);
    __nv_bfloat162 l23 = __floats2bfloat162_rn(v.z - f23.x, v.w - f23.y);
    bf16x4 hv; hv.a = h01; hv.b = h23;
    bf16x4 lv; lv.a = l01; lv.b = l23;
    *(bf16x4*)(hi + (size_t)t * 4) = hv;
    *(bf16x4*)(lo + (size_t)t * 4) = lv;
}

// W[K,N] fp32 -> Th/Tl [N,K] bf16 (transpose + split)
__global__ void split_transpose_kernel(const float* __restrict__ W,
                                       __nv_bfloat16* __restrict__ Th,
                                       __nv_bfloat16* __restrict__ Tl,
                                       int K, int N)
{
    __shared__ float t[32][33];
    const int n0 = blockIdx.x * 32, k0 = blockIdx.y * 32;
    const int tx = threadIdx.x, ty = threadIdx.y;  // 32 x 8
    #pragma unroll
    for (int j = 0; j < 32; j += 8)
        t[ty + j][tx] = W[(size_t)(k0 + ty + j) * N + n0 + tx];
    __syncthreads();
    #pragma unroll
    for (int j = 0; j < 32; j += 8) {
        int n = n0 + ty + j;
        float v = t[tx][ty + j];
        __nv_bfloat16 h = __float2bfloat16_rn(v);
        __nv_bfloat16 l = __float2bfloat16_rn(v - __bfloat162float(h));
        Th[(size_t)n * K + k0 + tx] = h;
        Tl[(size_t)n * K + k0 + tx] = l;
    }
}

// ---------------------------------------------------------------------------
// mma.sync split-bf16 GEMM: C[M,N] = (Ah+Al)[M,GK] @ ((Bh+Bl)[N,GK])^T + bias
// D += Ah·Bh + Ah·Bl + Al·Bh  (Al·Bl ~ 2^-18, dropped)
// Block 128x128, 8 warps (warp tile 64x32), K-chunk 64, cp.async dbl-buffer,
// SW128-swizzled smem rows (128B) for conflict-free ldmatrix.
// ---------------------------------------------------------------------------
#define KC       64
#define ARR_BYTES (128 * 128)            // 128 rows x 128B (64 bf16)
#define BUF_BYTES (4 * ARR_BYTES)        // Ah | Al | Bh | Bl = 64KB
#define GEMM_SMEM (2 * BUF_BYTES + 1024)
#define NCHUNK   (GK / KC)               // 16

__global__ __launch_bounds__(256, 1)
void gemm_tc_kernel(const __nv_bfloat16* __restrict__ Ah,
                    const __nv_bfloat16* __restrict__ Al,
                    const __nv_bfloat16* __restrict__ Bh,
                    const __nv_bfloat16* __restrict__ Bl,
                    const float* __restrict__ bias,
                    float* __restrict__ C, int N)
{
    extern __shared__ char smem_raw[];
    const uint32_t raw  = smem_to_u32(smem_raw);
    const uint32_t base = (raw + 1023u) & ~1023u;   // 1024-align for swizzle

    const int tid  = threadIdx.x;
    const int wid  = tid >> 5;
    const int lane = tid & 31;
    const int wm   = (wid & 1) * 64;    // warp m-offset in tile
    const int wn   = (wid >> 1) * 32;   // warp n-offset in tile
    const int m0   = blockIdx.y * 128;
    const int n0   = blockIdx.x * 128;

    auto issue_chunk = [&](int c, int buf) {
        const int k0 = c * KC;
        const uint32_t sb = base + buf * BUF_BYTES;
        #pragma unroll
        for (int p = 0; p < 4; ++p) {
            int idx = tid + p * 256;
            int r = idx >> 3, u = idx & 7;
            uint32_t soff = SWZ((uint32_t)(r * 128 + u * 16));
            size_t ga = (size_t)(m0 + r) * GK + k0 + u * 8;
            size_t gb = (size_t)(n0 + r) * GK + k0 + u * 8;
            CP_ASYNC16(sb +               soff, Ah + ga);
            CP_ASYNC16(sb + ARR_BYTES   + soff, Al + ga);
            CP_ASYNC16(sb + 2*ARR_BYTES + soff, Bh + gb);
            CP_ASYNC16(sb + 3*ARR_BYTES + soff, Bl + gb);
        }
    };

    float4 acc[4][4];
    #pragma unroll
    for (int i = 0; i < 4; ++i)
        #pragma unroll
        for (int j = 0; j < 4; ++j) acc[i][j] = make_float4(0.f,0.f,0.f,0.f);

    // ldmatrix lane addressing (within tile, before swizzle)
    const int a_row = lane & 15;            // + tile row base
    const int a_cb  = (lane >> 4) * 16;     // 0 or 16 bytes
    const int b_row = (lane & 7) + ((lane >> 4) & 1) * 8;
    const int b_cb  = ((lane >> 3) & 1) * 16;

    issue_chunk(0, 0);
    CP_COMMIT();

    for (int c = 0; c < NCHUNK; ++c) {
        const int buf = c & 1;
        if (c + 1 < NCHUNK) {
            issue_chunk(c + 1, buf ^ 1);
            CP_COMMIT();
            CP_WAIT(1);
        } else {
            CP_WAIT(0);
        }
        __syncthreads();

        const uint32_t sb = base + buf * BUF_BYTES;
        #pragma unroll
        for (int ks = 0; ks < 4; ++ks) {        // 4 x K=16 per chunk
            const int kb = ks * 32;             // byte offset along K
            uint32_t ah[4][4], al[4][4];
            #pragma unroll
            for (int mi = 0; mi < 4; ++mi) {
                uint32_t off = SWZ((uint32_t)((wm + mi*16 + a_row) * 128 + kb + a_cb));
                ldsm_x4(ah[mi][0], ah[mi][1], ah[mi][2], ah[mi][3], sb + off);
                ldsm_x4(al[mi][0], al[mi][1], al[mi][2], al[mi][3],
                        sb + ARR_BYTES + off);
            }
            uint32_t bh[2][4], bl[2][4];
            #pragma unroll
            for (int ni = 0; ni < 2; ++ni) {
                uint32_t off = SWZ((uint32_t)((wn + ni*16 + b_row) * 128 + kb + b_cb));
                ldsm_x4(bh[ni][0], bh[ni][1], bh[ni][2], bh[ni][3],
                        sb + 2*ARR_BYTES + off);
                ldsm_x4(bl[ni][0], bl[ni][1], bl[ni][2], bl[ni][3],
                        sb + 3*ARR_BYTES + off);
            }
            #pragma unroll
            for (int mi = 0; mi < 4; ++mi) {
                #pragma unroll
                for (int nj = 0; nj < 4; ++nj) {
                    const int g = nj >> 1, s = (nj & 1) * 2;
                    mma_bf16(acc[mi][nj], ah[mi], bh[g][s], bh[g][s+1]);
                    mma_bf16(acc[mi][nj], ah[mi], bl[g][s], bl[g][s+1]);
                    mma_bf16(acc[mi][nj], al[mi], bh[g][s], bh[g][s+1]);
                }
            }
        }
        __syncthreads();
    }

    // epilogue: fragment c: lane t -> rows t/4 & t/4+8, cols 2*(t&3)
    const int erow = lane >> 2;
    const int ecol = (lane & 3) * 2;
    #pragma unroll
    for (int mi = 0; mi < 4; ++mi) {
        #pragma unroll
        for (int nj = 0; nj < 4; ++nj) {
            int col = n0 + wn + nj * 8 + ecol;
            float b0 = __ldg(&bias[col]);
            float b1 = __ldg(&bias[col + 1]);
            size_t row = (size_t)(m0 + wm + mi * 16 + erow);
            float2 lo = make_float2(acc[mi][nj].x + b0, acc[mi][nj].y + b1);
            float2 hi = make_float2(acc[mi][nj].z + b0, acc[mi][nj].w + b1);
            *(float2*)(C + row * N + col)       = lo;
            *(float2*)(C + (row + 8) * N + col) = hi;
        }
    }
}

// ---------------------------------------------------------------------------
// Flash attention (fp32) — unchanged from round 2 (passing)
// ---------------------------------------------------------------------------
#define PADW 68
__global__ __launch_bounds__(256, 2)
void attn_kernel(const float* __restrict__ qkv, float* __restrict__ ctx)
{
    extern __shared__ float sm[];
    float* Qt = sm;                    // 64*68
    float* Kt = sm + 64*PADW;          // 64*68
    float* Pt = sm + 2*64*PADW;        // 64*68
    float* Vs = sm + 3*64*PADW;        // 64*64

    const int tid = threadIdx.x;
    const int tx  = tid & 15;
    const int ty  = tid >> 4;
    const int bh  = blockIdx.y;
    const int b   = bh >> 4;
    const int h   = bh & 15;
    const int s0  = blockIdx.x * 64;

    const float* qb = qkv + (size_t)(b*SEQ + s0) * QKVN + h*HD;

    #pragma unroll
    for (int p = 0; p < 4; p++) {
        int idx = tid + p*256;
        int r   = idx >> 4;
        int c4  = (idx & 15) * 4;
        float4 v = *(const float4*)(qb + (size_t)r*QKVN + c4);
        Qt[(c4+0)*PADW + r] = v.x * 0.125f;
        Qt[(c4+1)*PADW + r] = v.y * 0.125f;
        Qt[(c4+2)*PADW + r] = v.z * 0.125f;
        Qt[(c4+3)*PADW + r] = v.w * 0.125f;
    }

    float mrow[4], lrow[4], acc[4][4];
    #pragma unroll
    for (int i = 0; i < 4; i++) {
        mrow[i] = -1e30f; lrow[i] = 0.f;
        #pragma unroll
        for (int j = 0; j < 4; j++) acc[i][j] = 0.f;
    }

    for (int kt = 0; kt < SEQ; kt += 64) {
        const float* kb = qkv + (size_t)(b*SEQ + kt) * QKVN + DIM   + h*HD;
        const float* vb = qkv + (size_t)(b*SEQ + kt) * QKVN + 2*DIM + h*HD;

        __syncthreads();
        #pragma unroll
        for (int p = 0; p < 4; p++) {
            int idx = tid + p*256;
            int r   = idx >> 4;
            int c4  = (idx & 15) * 4;
            float4 kv = *(const float4*)(kb + (size_t)r*QKVN + c4);
            Kt[(c4+0)*PADW + r] = kv.x;
            Kt[(c4+1)*PADW + r] = kv.y;
            Kt[(c4+2)*PADW + r] = kv.z;
            Kt[(c4+3)*PADW + r] = kv.w;
            float4 vv = *(const float4*)(vb + (size_t)r*QKVN + c4);
            *(float4*)&Vs[r*64 + c4] = vv;
        }
        __syncthreads();

        float s[4][4];
        #pragma unroll
        for (int i = 0; i < 4; i++)
            #pragma unroll
            for (int j = 0; j < 4; j++) s[i][j] = 0.f;
        #pragma unroll 8
        for (int hd = 0; hd < 64; hd++) {
            float4 a4 = *(float4*)&Qt[hd*PADW + 4*ty];
            float4 b4 = *(float4*)&Kt[hd*PADW + 4*tx];
            float a[4] = {a4.x,a4.y,a4.z,a4.w};
            float bb[4] = {b4.x,b4.y,b4.z,b4.w};
            #pragma unroll
            for (int i = 0; i < 4; i++)
                #pragma unroll
                for (int j = 0; j < 4; j++)
                    s[i][j] = fmaf(a[i], bb[j], s[i][j]);
        }

        #pragma unroll
        for (int i = 0; i < 4; i++) {
            float rmax = fmaxf(fmaxf(s[i][0], s[i][1]), fmaxf(s[i][2], s[i][3]));
            #pragma unroll
            for (int off = 8; off >= 1; off >>= 1)
                rmax = fmaxf(rmax, __shfl_xor_sync(0xffffffffu, rmax, off));
            float mnew   = fmaxf(mrow[i], rmax);
            float factor = __expf(mrow[i] - mnew);
            mrow[i] = mnew;
            float ps = 0.f;
            #pragma unroll
            for (int j = 0; j < 4; j++) {
                float pv = __expf(s[i][j] - mnew);
                Pt[(4*tx + j)*PADW + 4*ty + i] = pv;
                ps += pv;
            }
            #pragma unroll
            for (int off = 8; off >= 1; off >>= 1)
                ps += __shfl_xor_sync(0xffffffffu, ps, off);
            lrow[i] = lrow[i] * factor + ps;
            #pragma unroll
            for (int j = 0; j < 4; j++) acc[i][j] *= factor;
        }
        __syncthreads();

        #pragma unroll 8
        for (int c = 0; c < 64; c++) {
            float4 a4 = *(float4*)&Pt[c*PADW + 4*ty];
            float4 b4 = *(float4*)&Vs[c*64 + 4*tx];
            float a[4] = {a4.x,a4.y,a4.z,a4.w};
            float bb[4] = {b4.x,b4.y,b4.z,b4.w};
            #pragma unroll
            for (int i = 0; i < 4; i++)
                #pragma unroll
                for (int j = 0; j < 4; j++)
                    acc[i][j] = fmaf(a[i], bb[j], acc[i][j]);
        }
    }

    #pragma unroll
    for (int i = 0; i < 4; i++) {
        float inv = 1.f / lrow[i];
        float4 o;
        o.x = acc[i][0]*inv; o.y = acc[i][1]*inv;
        o.z = acc[i][2]*inv; o.w = acc[i][3]*inv;
        size_t row = (size_t)(b*SEQ + s0 + 4*ty + i);
        *(float4*)(ctx + row*DIM + h*HD + 4*tx) = o;
    }
}

// ---------------------------------------------------------------------------
// Launch
// ---------------------------------------------------------------------------
extern "C" void kernel_launch(void* const* d_in, const int* in_sizes, int n_in,
                              void* d_out, int out_size)
{
    const float* x      = (const float*)d_in[0];
    const float* qkv_w  = (const float*)d_in[2];
    const float* qkv_b  = (const float*)d_in[3];
    const float* out_w  = (const float*)d_in[4];
    const float* out_b  = (const float*)d_in[5];
    float* out = (float*)d_out;

    float *qkv, *ctx;
    __nv_bfloat16 *ah, *al, *wqh, *wql, *woh, *wol;
    cudaGetSymbolAddress((void**)&qkv, g_qkv);
    cudaGetSymbolAddress((void**)&ctx, g_ctx);
    cudaGetSymbolAddress((void**)&ah,  g_ah);
    cudaGetSymbolAddress((void**)&al,  g_al);
    cudaGetSymbolAddress((void**)&wqh, g_wqh);
    cudaGetSymbolAddress((void**)&wql, g_wql);
    cudaGetSymbolAddress((void**)&woh, g_woh);
    cudaGetSymbolAddress((void**)&wol, g_wol);

    const int attn_smem = (3*64*PADW + 64*64) * (int)sizeof(float);   // 68608 B
    cudaFuncSetAttribute(attn_kernel,
                         cudaFuncAttributeMaxDynamicSharedMemorySize, attn_smem);
    cudaFuncSetAttribute(gemm_tc_kernel,
                         cudaFuncAttributeMaxDynamicSharedMemorySize, GEMM_SMEM);

    // 0) split inputs and weights into bf16 hi/lo
    split_rows_kernel<<<MROWS*DIM/(4*256), 256>>>(x, ah, al);
    split_transpose_kernel<<<dim3(QKVN/32, DIM/32), dim3(32,8)>>>(
        qkv_w, wqh, wql, GK, QKVN);
    split_transpose_kernel<<<dim3(DIM/32, DIM/32), dim3(32,8)>>>(
        out_w, woh, wol, GK, DIM);

    // 1) QKV projection (mma.sync): [4096,3072]
    gemm_tc_kernel<<<dim3(QKVN/128, MROWS/128), 256, GEMM_SMEM>>>(
        ah, al, wqh, wql, qkv_b, qkv, QKVN);

    // 2) attention
    attn_kernel<<<dim3(SEQ/64, BATCH*HEADS), 256, attn_smem>>>(qkv, ctx);

    // 3) split ctx, then output projection (mma.sync): [4096,1024]
    split_rows_kernel<<<MROWS*DIM/(4*256), 256>>>(ctx, ah, al);
    gemm_tc_kernel<<<dim3(DIM/128, MROWS/128), 256, GEMM_SMEM>>>(
        ah, al, woh, wol, out_b, out, DIM);
}

// round 7
// speedup vs baseline: 3.9171x; 2.9928x over previous
#include <cuda_runtime.h>
#include <cuda_bf16.h>
#include <cstdint>
#include <type_traits>
#include <math.h>

// Problem constants
#define BATCH 2
#define SEQ   2048
#define DIM   1024
#define HEADS 16
#define HD    64
#define MROWS (BATCH*SEQ)      // 4096
#define QKVN  (3*DIM)          // 3072
#define GK    1024             // K for both GEMMs

// ---------------------------------------------------------------------------
// Scratch (device globals — no allocation allowed)
// ---------------------------------------------------------------------------
__device__ __nv_bfloat16 g_qkv[MROWS * QKVN]; // bf16 q|k|v per row
__device__ __nv_bfloat16 g_ah[MROWS * DIM];   // activation hi (x, then ctx)
__device__ __nv_bfloat16 g_al[MROWS * DIM];   // activation lo
__device__ __nv_bfloat16 g_wqh[QKVN * DIM];   // qkv_w^T hi  [N=3072, K=1024]
__device__ __nv_bfloat16 g_wql[QKVN * DIM];   // qkv_w^T lo
__device__ __nv_bfloat16 g_woh[DIM * DIM];    // out_w^T hi  [N=1024, K=1024]
__device__ __nv_bfloat16 g_wol[DIM * DIM];    // out_w^T lo

// ---------------------------------------------------------------------------
// Baseline-PTX helpers (sm_80-era ISA only — compute_100 target rejects tcgen05)
// ---------------------------------------------------------------------------
__device__ __forceinline__ uint32_t smem_to_u32(const void* smem_ptr) {
    uint32_t addr;
    asm("{ .reg .u64 tmp; cvta.to.shared.u64 tmp, %1; cvt.u32.u64 %0, tmp; }"
        : "=r"(addr) : "l"(smem_ptr));
    return addr;
}

#define SWZ(byte_offset) ((byte_offset) ^ (((byte_offset) >> 3) & 0x70))

__device__ __forceinline__ void ldsm_x4(uint32_t& r0, uint32_t& r1,
                                        uint32_t& r2, uint32_t& r3,
                                        uint32_t addr) {
    asm volatile("ldmatrix.sync.aligned.m8n8.x4.shared.b16 {%0,%1,%2,%3}, [%4];"
                 : "=r"(r0), "=r"(r1), "=r"(r2), "=r"(r3) : "r"(addr));
}

__device__ __forceinline__ void ldsm_x4_t(uint32_t& r0, uint32_t& r1,
                                          uint32_t& r2, uint32_t& r3,
                                          uint32_t addr) {
    asm volatile("ldmatrix.sync.aligned.m8n8.x4.trans.shared.b16 {%0,%1,%2,%3}, [%4];"
                 : "=r"(r0), "=r"(r1), "=r"(r2), "=r"(r3) : "r"(addr));
}

__device__ __forceinline__ void mma_bf16(float4& c, const uint32_t a[4],
                                         uint32_t b0, uint32_t b1) {
    asm volatile(
        "mma.sync.aligned.m16n8k16.row.col.f32.bf16.bf16.f32 "
        "{%0,%1,%2,%3}, {%4,%5,%6,%7}, {%8,%9}, {%0,%1,%2,%3};"
        : "+f"(c.x), "+f"(c.y), "+f"(c.z), "+f"(c.w)
        : "r"(a[0]), "r"(a[1]), "r"(a[2]), "r"(a[3]), "r"(b0), "r"(b1));
}

__device__ __forceinline__ uint32_t pack_bf16(float a, float b) {
    __nv_bfloat162 t = __floats2bfloat162_rn(a, b);
    return *(uint32_t*)&t;
}

#define CP_ASYNC16(dst, src) \
    asm volatile("cp.async.cg.shared.global [%0], [%1], 16;" \
                 :: "r"(dst), "l"(src))
#define CP_COMMIT() asm volatile("cp.async.commit_group;" ::: "memory")
#define CP_WAIT(n)  asm volatile("cp.async.wait_group %0;" :: "n"(n) : "memory")

// ---------------------------------------------------------------------------
// split kernels: fp32 -> (bf16 hi, bf16 lo)
// ---------------------------------------------------------------------------
struct alignas(8) bf16x4 { __nv_bfloat162 a, b; };

__global__ void split_rows_kernel(const float* __restrict__ in,
                                  __nv_bfloat16* __restrict__ hi,
                                  __nv_bfloat16* __restrict__ lo)
{
    int t = blockIdx.x * blockDim.x + threadIdx.x;
    float4 v = *(const float4*)(in + (size_t)t * 4);
    __nv_bfloat162 h01 = __floats2bfloat162_rn(v.x, v.y);
    __nv_bfloat162 h23 = __floats2bfloat162_rn(v.z, v.w);
    float2 f01 = __bfloat1622float2(h01);
    float2 f23 = __bfloat1622float2(h23);
    __nv_bfloat162 l01 = __floats2bfloat162_rn(v.x - f01.x, v.y - f01.y);
    __nv_bfloat162 l23 = __floats2bfloat162_rn(v.z - f23.x, v.w - f23.y);
    bf16x4 hv; hv.a = h01; hv.b = h23;
    bf16x4 lv; lv.a = l01; lv.b = l23;
    *(bf16x4*)(hi + (size_t)t * 4) = hv;
    *(bf16x4*)(lo + (size_t)t * 4) = lv;
}

// W[K,N] fp32 -> Th/Tl [N,K] bf16 (transpose + split)
__global__ void split_transpose_kernel(const float* __restrict__ W,
                                       __nv_bfloat16* __restrict__ Th,
                                       __nv_bfloat16* __restrict__ Tl,
                                       int K, int N)
{
    __shared__ float t[32][33];
    const int n0 = blockIdx.x * 32, k0 = blockIdx.y * 32;
    const int tx = threadIdx.x, ty = threadIdx.y;  // 32 x 8
    #pragma unroll
    for (int j = 0; j < 32; j += 8)
        t[ty + j][tx] = W[(size_t)(k0 + ty + j) * N + n0 + tx];
    __syncthreads();
    #pragma unroll
    for (int j = 0; j < 32; j += 8) {
        int n = n0 + ty + j;
        float v = t[tx][ty + j];
        __nv_bfloat16 h = __float2bfloat16_rn(v);
        __nv_bfloat16 l = __float2bfloat16_rn(v - __bfloat162float(h));
        Th[(size_t)n * K + k0 + tx] = h;
        Tl[(size_t)n * K + k0 + tx] = l;
    }
}

// ---------------------------------------------------------------------------
// mma.sync split-bf16 GEMM: C[M,N] = (Ah+Al)[M,GK] @ ((Bh+Bl)[N,GK])^T + bias
// OutT = float (fp32 C) or __nv_bfloat16 (bf16 C).
// ---------------------------------------------------------------------------
#define KC       64
#define ARR_BYTES (128 * 128)            // 128 rows x 128B (64 bf16)
#define BUF_BYTES (4 * ARR_BYTES)        // Ah | Al | Bh | Bl = 64KB
#define GEMM_SMEM (2 * BUF_BYTES + 1024)
#define NCHUNK   (GK / KC)               // 16

template<typename OutT>
__global__ __launch_bounds__(256, 1)
void gemm_tc_kernel(const __nv_bfloat16* __restrict__ Ah,
                    const __nv_bfloat16* __restrict__ Al,
                    const __nv_bfloat16* __restrict__ Bh,
                    const __nv_bfloat16* __restrict__ Bl,
                    const float* __restrict__ bias,
                    OutT* __restrict__ C, int N)
{
    extern __shared__ char smem_raw[];
    const uint32_t raw  = smem_to_u32(smem_raw);
    const uint32_t base = (raw + 1023u) & ~1023u;

    const int tid  = threadIdx.x;
    const int wid  = tid >> 5;
    const int lane = tid & 31;
    const int wm   = (wid & 1) * 64;
    const int wn   = (wid >> 1) * 32;
    const int m0   = blockIdx.y * 128;
    const int n0   = blockIdx.x * 128;

    auto issue_chunk = [&](int c, int buf) {
        const int k0 = c * KC;
        const uint32_t sb = base + buf * BUF_BYTES;
        #pragma unroll
        for (int p = 0; p < 4; ++p) {
            int idx = tid + p * 256;
            int r = idx >> 3, u = idx & 7;
            uint32_t soff = SWZ((uint32_t)(r * 128 + u * 16));
            size_t ga = (size_t)(m0 + r) * GK + k0 + u * 8;
            size_t gb = (size_t)(n0 + r) * GK + k0 + u * 8;
            CP_ASYNC16(sb +               soff, Ah + ga);
            CP_ASYNC16(sb + ARR_BYTES   + soff, Al + ga);
            CP_ASYNC16(sb + 2*ARR_BYTES + soff, Bh + gb);
            CP_ASYNC16(sb + 3*ARR_BYTES + soff, Bl + gb);
        }
    };

    float4 acc[4][4];
    #pragma unroll
    for (int i = 0; i < 4; ++i)
        #pragma unroll
        for (int j = 0; j < 4; ++j) acc[i][j] = make_float4(0.f,0.f,0.f,0.f);

    const int a_row = lane & 15;
    const int a_cb  = (lane >> 4) * 16;
    const int b_row = (lane & 7) + ((lane >> 4) & 1) * 8;
    const int b_cb  = ((lane >> 3) & 1) * 16;

    issue_chunk(0, 0);
    CP_COMMIT();

    for (int c = 0; c < NCHUNK; ++c) {
        const int buf = c & 1;
        if (c + 1 < NCHUNK) {
            issue_chunk(c + 1, buf ^ 1);
            CP_COMMIT();
            CP_WAIT(1);
        } else {
            CP_WAIT(0);
        }
        __syncthreads();

        const uint32_t sb = base + buf * BUF_BYTES;
        #pragma unroll
        for (int ks = 0; ks < 4; ++ks) {
            const int kb = ks * 32;
            uint32_t ah[4][4], al[4][4];
            #pragma unroll
            for (int mi = 0; mi < 4; ++mi) {
                uint32_t off = SWZ((uint32_t)((wm + mi*16 + a_row) * 128 + kb + a_cb));
                ldsm_x4(ah[mi][0], ah[mi][1], ah[mi][2], ah[mi][3], sb + off);
                ldsm_x4(al[mi][0], al[mi][1], al[mi][2], al[mi][3],
                        sb + ARR_BYTES + off);
            }
            uint32_t bh[2][4], bl[2][4];
            #pragma unroll
            for (int ni = 0; ni < 2; ++ni) {
                uint32_t off = SWZ((uint32_t)((wn + ni*16 + b_row) * 128 + kb + b_cb));
                ldsm_x4(bh[ni][0], bh[ni][1], bh[ni][2], bh[ni][3],
                        sb + 2*ARR_BYTES + off);
                ldsm_x4(bl[ni][0], bl[ni][1], bl[ni][2], bl[ni][3],
                        sb + 3*ARR_BYTES + off);
            }
            #pragma unroll
            for (int mi = 0; mi < 4; ++mi) {
                #pragma unroll
                for (int nj = 0; nj < 4; ++nj) {
                    const int g = nj >> 1, s = (nj & 1) * 2;
                    mma_bf16(acc[mi][nj], ah[mi], bh[g][s], bh[g][s+1]);
                    mma_bf16(acc[mi][nj], ah[mi], bl[g][s], bl[g][s+1]);
                    mma_bf16(acc[mi][nj], al[mi], bh[g][s], bh[g][s+1]);
                }
            }
        }
        __syncthreads();
    }

    const int erow = lane >> 2;
    const int ecol = (lane & 3) * 2;
    #pragma unroll
    for (int mi = 0; mi < 4; ++mi) {
        #pragma unroll
        for (int nj = 0; nj < 4; ++nj) {
            int col = n0 + wn + nj * 8 + ecol;
            float b0 = __ldg(&bias[col]);
            float b1 = __ldg(&bias[col + 1]);
            size_t row = (size_t)(m0 + wm + mi * 16 + erow);
            if constexpr (std::is_same<OutT, float>::value) {
                *(float2*)(C + row * N + col) =
                    make_float2(acc[mi][nj].x + b0, acc[mi][nj].y + b1);
                *(float2*)(C + (row + 8) * N + col) =
                    make_float2(acc[mi][nj].z + b0, acc[mi][nj].w + b1);
            } else {
                *(__nv_bfloat162*)(C + row * N + col) =
                    __floats2bfloat162_rn(acc[mi][nj].x + b0, acc[mi][nj].y + b1);
                *(__nv_bfloat162*)(C + (row + 8) * N + col) =
                    __floats2bfloat162_rn(acc[mi][nj].z + b0, acc[mi][nj].w + b1);
            }
        }
    }
}

// ---------------------------------------------------------------------------
// Tensor-core flash attention (bf16 mma, fp32 accumulate)
// Block: 128 queries of one (b,h); 8 warps x 16 q-rows. 64-key tiles,
// cp.async double-buffered K/V. P fragments stay in registers (score C-frag
// == P A-frag layout). V B-frags via ldmatrix.trans. Scale 1/8 folded in exp.
// Epilogue writes ctx hi/lo bf16 splits for the out-projection.
// ---------------------------------------------------------------------------
#define ATT_QB    (128*128)              // Q tile: 16KB
#define ATT_TILEB (64*128)               // K or V tile: 8KB
#define ATT_SMEM  (ATT_QB + 4*ATT_TILEB + 1024 + 64)
#define NKT       (SEQ/64)               // 32 key tiles

__global__ __launch_bounds__(256, 1)
void attn_tc_kernel(const __nv_bfloat16* __restrict__ qkv,
                    __nv_bfloat16* __restrict__ ch,
                    __nv_bfloat16* __restrict__ cl)
{
    extern __shared__ char smem_raw[];
    const uint32_t raw  = smem_to_u32(smem_raw);
    const uint32_t base = (raw + 1023u) & ~1023u;
    char* cbase = smem_raw + (base - raw);

    const int tid = threadIdx.x, wid = tid >> 5, lane = tid & 31;
    const int bh = blockIdx.y, b = bh >> 4, h = bh & 15;
    const int q0 = blockIdx.x * 128;

    // Q tile -> smem (SW128 swizzled)
    const __nv_bfloat16* qbase = qkv + (size_t)(b*SEQ + q0) * QKVN + h*HD;
    #pragma unroll
    for (int p = 0; p < 4; ++p) {
        int idx = tid + p * 256;
        int r = idx >> 3, u = idx & 7;
        *(uint4*)(cbase + SWZ((uint32_t)(r*128 + u*16))) =
            *(const uint4*)(qbase + (size_t)r * QKVN + u*8);
    }

    const uint32_t sKV0 = base + ATT_QB;
    auto issue_kv = [&](int kt, int buf) {
        const __nv_bfloat16* kb_ = qkv + (size_t)(b*SEQ + kt*64) * QKVN + DIM + h*HD;
        const __nv_bfloat16* vb_ = kb_ + DIM;
        uint32_t sK = sKV0 + buf * (2*ATT_TILEB);
        #pragma unroll
        for (int p = 0; p < 4; ++p) {
            int idx = tid + p * 256;
            int mat = idx >> 9;            // 0: K, 1: V
            int r   = (idx >> 3) & 63;
            int u   = idx & 7;
            const __nv_bfloat16* src = (mat ? vb_ : kb_) + (size_t)r * QKVN + u*8;
            CP_ASYNC16(sK + mat*ATT_TILEB + SWZ((uint32_t)(r*128 + u*16)), src);
        }
    };

    issue_kv(0, 0);
    CP_COMMIT();
    __syncthreads();   // Q visible

    // Q A-fragments, loaded once
    const int ar = lane & 15, acb = (lane >> 4) * 16;
    uint32_t qf[4][4];
    #pragma unroll
    for (int ks = 0; ks < 4; ++ks) {
        uint32_t off = SWZ((uint32_t)((16*wid + ar)*128 + ks*32 + acb));
        ldsm_x4(qf[ks][0], qf[ks][1], qf[ks][2], qf[ks][3], base + off);
    }

    float4 ctx[8];
    #pragma unroll
    for (int nj = 0; nj < 8; ++nj) ctx[nj] = make_float4(0.f,0.f,0.f,0.f);
    float m0 = -1e30f, m1 = -1e30f, l0 = 0.f, l1 = 0.f;

    const int br  = (lane & 7) + ((lane >> 4) & 1) * 8;
    const int bcb = ((lane >> 3) & 1) * 16;

    for (int t = 0; t < NKT; ++t) {
        const int buf = t & 1;
        if (t + 1 < NKT) { issue_kv(t + 1, buf ^ 1); CP_COMMIT(); CP_WAIT(1); }
        else             { CP_WAIT(0); }
        __syncthreads();

        const uint32_t sK = sKV0 + buf * (2*ATT_TILEB);
        const uint32_t sV = sK + ATT_TILEB;

        // scores S[16,64] per warp
        float4 sc[8];
        #pragma unroll
        for (int nj = 0; nj < 8; ++nj) sc[nj] = make_float4(0.f,0.f,0.f,0.f);
        #pragma unroll
        for (int ks = 0; ks < 4; ++ks) {
            uint32_t kf[4][4];
            #pragma unroll
            for (int kg = 0; kg < 4; ++kg) {
                uint32_t off = SWZ((uint32_t)((kg*16 + br)*128 + ks*32 + bcb));
                ldsm_x4(kf[kg][0], kf[kg][1], kf[kg][2], kf[kg][3], sK + off);
            }
            #pragma unroll
            for (int nj = 0; nj < 8; ++nj) {
                const int g = nj >> 1, s = (nj & 1) * 2;
                mma_bf16(sc[nj], qf[ks], kf[g][s], kf[g][s+1]);
            }
        }

        // online softmax (raw-score domain; 1/8 scale inside exp)
        float mx0 = -1e30f, mx1 = -1e30f;
        #pragma unroll
        for (int nj = 0; nj < 8; ++nj) {
            mx0 = fmaxf(mx0, fmaxf(sc[nj].x, sc[nj].y));
            mx1 = fmaxf(mx1, fmaxf(sc[nj].z, sc[nj].w));
        }
        mx0 = fmaxf(mx0, __shfl_xor_sync(0xffffffffu, mx0, 1));
        mx0 = fmaxf(mx0, __shfl_xor_sync(0xffffffffu, mx0, 2));
        mx1 = fmaxf(mx1, __shfl_xor_sync(0xffffffffu, mx1, 1));
        mx1 = fmaxf(mx1, __shfl_xor_sync(0xffffffffu, mx1, 2));
        float nm0 = fmaxf(m0, mx0), nm1 = fmaxf(m1, mx1);
        float f0 = __expf(0.125f * (m0 - nm0));
        float f1 = __expf(0.125f * (m1 - nm1));
        m0 = nm0; m1 = nm1;

        float s0 = 0.f, s1 = 0.f;
        #pragma unroll
        for (int nj = 0; nj < 8; ++nj) {
            sc[nj].x = __expf(0.125f * (sc[nj].x - nm0));
            sc[nj].y = __expf(0.125f * (sc[nj].y - nm0));
            sc[nj].z = __expf(0.125f * (sc[nj].z - nm1));
            sc[nj].w = __expf(0.125f * (sc[nj].w - nm1));
            s0 += sc[nj].x + sc[nj].y;
            s1 += sc[nj].z + sc[nj].w;
        }
        s0 += __shfl_xor_sync(0xffffffffu, s0, 1);
        s0 += __shfl_xor_sync(0xffffffffu, s0, 2);
        s1 += __shfl_xor_sync(0xffffffffu, s1, 1);
        s1 += __shfl_xor_sync(0xffffffffu, s1, 2);
        l0 = l0 * f0 + s0;
        l1 = l1 * f1 + s1;
        #pragma unroll
        for (int nj = 0; nj < 8; ++nj) {
            ctx[nj].x *= f0; ctx[nj].y *= f0;
            ctx[nj].z *= f1; ctx[nj].w *= f1;
        }

        // P A-fragments directly from score C-fragments
        uint32_t pf[4][4];
        #pragma unroll
        for (int ks = 0; ks < 4; ++ks) {
            pf[ks][0] = pack_bf16(sc[2*ks].x,   sc[2*ks].y);
            pf[ks][1] = pack_bf16(sc[2*ks].z,   sc[2*ks].w);
            pf[ks][2] = pack_bf16(sc[2*ks+1].x, sc[2*ks+1].y);
            pf[ks][3] = pack_bf16(sc[2*ks+1].z, sc[2*ks+1].w);
        }

        // ctx += P @ V  (V B-frags via ldmatrix.trans of key-major tile)
        #pragma unroll
        for (int ks = 0; ks < 4; ++ks) {
            uint32_t vf[4][4];
            #pragma unroll
            for (int dp = 0; dp < 4; ++dp) {
                uint32_t off = SWZ((uint32_t)((16*ks + ar)*128 + dp*32 + acb));
                ldsm_x4_t(vf[dp][0], vf[dp][1], vf[dp][2], vf[dp][3], sV + off);
            }
            #pragma unroll
            for (int nj = 0; nj < 8; ++nj) {
                const int g = nj >> 1, s = (nj & 1) * 2;
                mma_bf16(ctx[nj], pf[ks], vf[g][s], vf[g][s+1]);
            }
        }
        __syncthreads();
    }

    // epilogue: normalize, split hi/lo, write to g_ah/g_al
    // NOTE: row index includes the batch offset (b*SEQ) — this was the
    // round-6 bug (batch-1 rows overwrote batch-0, rows 2048+ never written).
    const float inv0 = 1.f / l0, inv1 = 1.f / l1;
    const int r0   = b*SEQ + q0 + 16*wid + (lane >> 2);
    const int colb = h*HD + 2*(lane & 3);
    #pragma unroll
    for (int nj = 0; nj < 8; ++nj) {
        int col = colb + 8*nj;
        float v0 = ctx[nj].x * inv0, v1 = ctx[nj].y * inv0;
        float v2 = ctx[nj].z * inv1, v3 = ctx[nj].w * inv1;
        __nv_bfloat162 h01 = __floats2bfloat162_rn(v0, v1);
        __nv_bfloat162 h23 = __floats2bfloat162_rn(v2, v3);
        float2 f01 = __bfloat1622float2(h01);
        float2 f23 = __bfloat1622float2(h23);
        __nv_bfloat162 lo01 = __floats2bfloat162_rn(v0 - f01.x, v1 - f01.y);
        __nv_bfloat162 lo23 = __floats2bfloat162_rn(v2 - f23.x, v3 - f23.y);
        *(__nv_bfloat162*)(ch + (size_t)r0 * DIM + col)       = h01;
        *(__nv_bfloat162*)(cl + (size_t)r0 * DIM + col)       = lo01;
        *(__nv_bfloat162*)(ch + (size_t)(r0+8) * DIM + col)   = h23;
        *(__nv_bfloat162*)(cl + (size_t)(r0+8) * DIM + col)   = lo23;
    }
}

// ---------------------------------------------------------------------------
// Launch
// ---------------------------------------------------------------------------
extern "C" void kernel_launch(void* const* d_in, const int* in_sizes, int n_in,
                              void* d_out, int out_size)
{
    const float* x      = (const float*)d_in[0];
    const float* qkv_w  = (const float*)d_in[2];
    const float* qkv_b  = (const float*)d_in[3];
    const float* out_w  = (const float*)d_in[4];
    const float* out_b  = (const float*)d_in[5];
    float* out = (float*)d_out;

    __nv_bfloat16 *qkv, *ah, *al, *wqh, *wql, *woh, *wol;
    cudaGetSymbolAddress((void**)&qkv, g_qkv);
    cudaGetSymbolAddress((void**)&ah,  g_ah);
    cudaGetSymbolAddress((void**)&al,  g_al);
    cudaGetSymbolAddress((void**)&wqh, g_wqh);
    cudaGetSymbolAddress((void**)&wql, g_wql);
    cudaGetSymbolAddress((void**)&woh, g_woh);
    cudaGetSymbolAddress((void**)&wol, g_wol);

    cudaFuncSetAttribute(gemm_tc_kernel<__nv_bfloat16>,
                         cudaFuncAttributeMaxDynamicSharedMemorySize, GEMM_SMEM);
    cudaFuncSetAttribute(gemm_tc_kernel<float>,
                         cudaFuncAttributeMaxDynamicSharedMemorySize, GEMM_SMEM);
    cudaFuncSetAttribute(attn_tc_kernel,
                         cudaFuncAttributeMaxDynamicSharedMemorySize, ATT_SMEM);

    // 0) split x and weights into bf16 hi/lo
    split_rows_kernel<<<MROWS*DIM/(4*256), 256>>>(x, ah, al);
    split_transpose_kernel<<<dim3(QKVN/32, DIM/32), dim3(32,8)>>>(
        qkv_w, wqh, wql, GK, QKVN);
    split_transpose_kernel<<<dim3(DIM/32, DIM/32), dim3(32,8)>>>(
        out_w, woh, wol, GK, DIM);

    // 1) QKV projection -> bf16 qkv
    gemm_tc_kernel<__nv_bfloat16><<<dim3(QKVN/128, MROWS/128), 256, GEMM_SMEM>>>(
        ah, al, wqh, wql, qkv_b, qkv, QKVN);

    // 2) tensor-core attention; writes ctx hi/lo splits into ah/al
    attn_tc_kernel<<<dim3(SEQ/128, BATCH*HEADS), 256, ATT_SMEM>>>(qkv, ah, al);

    // 3) output projection (fp32 out)
    gemm_tc_kernel<float><<<dim3(DIM/128, MROWS/128), 256, GEMM_SMEM>>>(
        ah, al, woh, wol, out_b, out, DIM);
}